// round 2
// baseline (speedup 1.0000x reference)
#include <cuda_runtime.h>
#include <cuda_bf16.h>

#define N_BODIES 512
#define HID 128
#define IN_DIM 7
#define OUT_DIM (N_BODIES * 6)      // 3072
#define KDIM (N_BODIES * HID)       // 65536
#define NEG_SLOPE 0.2f

// ---- scratch (no allocations allowed) ----
__device__ float g_Sx[IN_DIM];
__device__ float g_h1[N_BODIES * HID];
__device__ float g_p1[8 * HID];          // partial column sums of h1
__device__ float g_h2[N_BODIES * HID];
__device__ float g_xh[N_BODIES * 2 * HID];   // GAT projected features [N,256]
__device__ float g_as[N_BODIES * 2];
__device__ float g_ad[N_BODIES * 2];
__device__ float g_h3[KDIM];             // final node features (flattened fc input)
#define KSPLITS 512
__device__ float g_part[KSPLITS * OUT_DIM];  // 6 MB matvec partials

// ============================================================
// 1) column sums of x [512,7]
__global__ void k_sumx(const float* __restrict__ x) {
    int w = threadIdx.x >> 5, lane = threadIdx.x & 31;
    if (w < IN_DIM) {
        float s = 0.f;
        for (int i = lane; i < N_BODIES; i += 32) s += x[i * IN_DIM + w];
        #pragma unroll
        for (int o = 16; o; o >>= 1) s += __shfl_xor_sync(0xffffffffu, s, o);
        if (lane == 0) g_Sx[w] = s;
    }
}

// 2) h1 = relu( (S - x_i)@W_rel1 + b_rel1 + x_i@W_root1 + x_i@W_res + b_res )
__global__ void k_h1(const float* __restrict__ x,
                     const float* __restrict__ W_res, const float* __restrict__ b_res,
                     const float* __restrict__ W_rel1, const float* __restrict__ b_rel1,
                     const float* __restrict__ W_root1) {
    int i = blockIdx.x, c = threadIdx.x;
    __shared__ float sx[IN_DIM];
    if (c < IN_DIM) sx[c] = x[i * IN_DIM + c];
    __syncthreads();
    float acc = b_rel1[c] + b_res[c];
    #pragma unroll
    for (int d = 0; d < IN_DIM; d++) {
        float xd = sx[d];
        acc += (g_Sx[d] - xd) * W_rel1[d * HID + c]
             + xd * (W_root1[d * HID + c] + W_res[d * HID + c]);
    }
    g_h1[i * HID + c] = fmaxf(acc, 0.f);
}

// 3) partial column sums of h1 (8 partials of 64 rows)
__global__ void k_part1() {
    int p = blockIdx.x, c = threadIdx.x;
    float s = 0.f;
    int i0 = p * 64;
    #pragma unroll 8
    for (int i = 0; i < 64; i++) s += g_h1[(i0 + i) * HID + c];
    g_p1[p * HID + c] = s;
}

// 4) h2 = relu( (S1 - h1_i)@W_rel2 + b_rel2 + h1_i@W_root2 )
__global__ void k_h2(const float* __restrict__ W_rel2, const float* __restrict__ b_rel2,
                     const float* __restrict__ W_root2) {
    int i = blockIdx.x, c = threadIdx.x;
    __shared__ float sh[HID], ss[HID];
    sh[c] = g_h1[i * HID + c];
    float s1 = 0.f;
    #pragma unroll
    for (int p = 0; p < 8; p++) s1 += g_p1[p * HID + c];
    ss[c] = s1;
    __syncthreads();
    float acc = b_rel2[c];
    #pragma unroll 4
    for (int d = 0; d < HID; d++) {
        float hv = sh[d];
        acc += (ss[d] - hv) * W_rel2[d * HID + c] + hv * W_root2[d * HID + c];
    }
    g_h2[i * HID + c] = fmaxf(acc, 0.f);
}

// 5) GAT projection xh = h2 @ W_gat [512,256]; logits a_s,a_d per (node,head)
__global__ void k_gatpre(const float* __restrict__ W_gat,
                         const float* __restrict__ att_src,
                         const float* __restrict__ att_dst) {
    int i = blockIdx.x, t = threadIdx.x;          // 256 threads
    __shared__ float sh[HID];
    __shared__ float red[256];
    if (t < HID) sh[t] = g_h2[i * HID + t];
    __syncthreads();
    float acc = 0.f;
    #pragma unroll 4
    for (int d = 0; d < HID; d++) acc += sh[d] * W_gat[d * 256 + t];
    g_xh[i * 256 + t] = acc;
    int h = t >> 7, cc = t & 127;
    red[t] = acc * att_src[h * HID + cc];
    __syncthreads();
    for (int o = 64; o >= 1; o >>= 1) {
        if (cc < o) red[t] += red[t + o];
        __syncthreads();
    }
    if (cc == 0) g_as[i * 2 + h] = red[t];
    __syncthreads();
    red[t] = acc * att_dst[h * HID + cc];
    __syncthreads();
    for (int o = 64; o >= 1; o >>= 1) {
        if (cc < o) red[t] += red[t + o];
        __syncthreads();
    }
    if (cc == 0) g_ad[i * 2 + h] = red[t];
}

// 6) dense-softmax GAT aggregation: 4 dst nodes per block, 256 threads
__global__ void __launch_bounds__(256) k_gat(const float* __restrict__ b_gat) {
    __shared__ float al[8 * 512];    // alpha[pair = d*2+h][j], 16 KB
    int i0 = blockIdx.x * 4;
    int w = threadIdx.x >> 5, lane = threadIdx.x & 31;

    // phase 1: warp w computes softmax weights for pair (dst i0+w/2, head w&1)
    {
        int d = w >> 1, h = w & 1;
        float ad = g_ad[(i0 + d) * 2 + h];
        float ev[16];
        float m = -1e30f;
        #pragma unroll
        for (int q = 0; q < 16; q++) {
            int j = lane + q * 32;
            float t = g_as[j * 2 + h] + ad;
            float e = t > 0.f ? t : NEG_SLOPE * t;
            ev[q] = e;
            m = fmaxf(m, e);
        }
        #pragma unroll
        for (int o = 16; o; o >>= 1) m = fmaxf(m, __shfl_xor_sync(0xffffffffu, m, o));
        float z = 0.f;
        #pragma unroll
        for (int q = 0; q < 16; q++) { float wv = __expf(ev[q] - m); ev[q] = wv; z += wv; }
        #pragma unroll
        for (int o = 16; o; o >>= 1) z += __shfl_xor_sync(0xffffffffu, z, o);
        float inv = 1.f / z;
        #pragma unroll
        for (int q = 0; q < 16; q++) al[w * 512 + lane + q * 32] = ev[q] * inv;
    }
    __syncthreads();

    // phase 2: accumulate out[d][t] = sum_j alpha[d][h][j] * xh[j][t]
    int h = threadIdx.x >> 7;
    const float* xcol = g_xh + threadIdx.x;
    const float* A0 = al + (0 + h) * 512;
    const float* A1 = al + (2 + h) * 512;
    const float* A2 = al + (4 + h) * 512;
    const float* A3 = al + (6 + h) * 512;
    float a0 = 0.f, a1 = 0.f, a2 = 0.f, a3 = 0.f;
    #pragma unroll 4
    for (int j = 0; j < 512; j += 2) {
        float x0 = xcol[(size_t)j * 256];
        float x1 = xcol[(size_t)(j + 1) * 256];
        a0 += A0[j] * x0 + A0[j + 1] * x1;
        a1 += A1[j] * x0 + A1[j + 1] * x1;
        a2 += A2[j] * x0 + A2[j + 1] * x1;
        a3 += A3[j] * x0 + A3[j + 1] * x1;
    }
    __syncthreads();  // done reading alpha; reuse shared as output staging
    al[0 * 256 + threadIdx.x] = a0;
    al[1 * 256 + threadIdx.x] = a1;
    al[2 * 256 + threadIdx.x] = a2;
    al[3 * 256 + threadIdx.x] = a3;
    __syncthreads();
    if (threadIdx.x < HID) {
        int c = threadIdx.x;
        float bg = b_gat[c];
        #pragma unroll
        for (int d = 0; d < 4; d++) {
            float v = 0.5f * (al[d * 256 + c] + al[d * 256 + 128 + c]) + bg;
            g_h3[(i0 + d) * HID + c] = fmaxf(v, 0.f);
        }
    }
}

// 7) split-K matvec: out_partial[b] = sum over 128 rows of v[k] * W_fc[k, :]
//    768 threads, each owns ONE float4 column (768*4 = 3072 cols); 512 K-splits.
__global__ void __launch_bounds__(768) k_matvec(const float* __restrict__ Wfc) {
    int b = blockIdx.x, t = threadIdx.x;
    __shared__ float v[128];
    int k0 = b * 128;
    if (t < 128) v[t] = g_h3[k0 + t];
    __syncthreads();
    const float4* W4 = (const float4*)Wfc;     // row = 768 float4
    size_t base = (size_t)k0 * 768 + t;
    float4 s0 = {0,0,0,0}, s1 = {0,0,0,0}, s2 = {0,0,0,0}, s3 = {0,0,0,0};
    #pragma unroll 4
    for (int kk = 0; kk < 128; kk += 4) {
        float4 w0 = W4[base + (size_t)(kk + 0) * 768];
        float4 w1 = W4[base + (size_t)(kk + 1) * 768];
        float4 w2 = W4[base + (size_t)(kk + 2) * 768];
        float4 w3 = W4[base + (size_t)(kk + 3) * 768];
        float v0 = v[kk], v1 = v[kk + 1], v2 = v[kk + 2], v3 = v[kk + 3];
        s0.x += v0 * w0.x; s0.y += v0 * w0.y; s0.z += v0 * w0.z; s0.w += v0 * w0.w;
        s1.x += v1 * w1.x; s1.y += v1 * w1.y; s1.z += v1 * w1.z; s1.w += v1 * w1.w;
        s2.x += v2 * w2.x; s2.y += v2 * w2.y; s2.z += v2 * w2.z; s2.w += v2 * w2.w;
        s3.x += v3 * w3.x; s3.y += v3 * w3.y; s3.z += v3 * w3.z; s3.w += v3 * w3.w;
    }
    float4 r;
    r.x = s0.x + s1.x + s2.x + s3.x;
    r.y = s0.y + s1.y + s2.y + s3.y;
    r.z = s0.z + s1.z + s2.z + s3.z;
    r.w = s0.w + s1.w + s2.w + s3.w;
    ((float4*)g_part)[(size_t)b * 768 + t] = r;
}

// 8) reduce partials + bias -> out
__global__ void k_reduce(const float* __restrict__ b_fc, float* __restrict__ out) {
    int o = blockIdx.x * 256 + threadIdx.x;
    float acc = b_fc[o];
    #pragma unroll 8
    for (int s = 0; s < KSPLITS; s++) acc += g_part[(size_t)s * OUT_DIM + o];
    out[o] = acc;
}

extern "C" void kernel_launch(void* const* d_in, const int* in_sizes, int n_in,
                              void* d_out, int out_size) {
    const float* x       = (const float*)d_in[0];
    // d_in[1] = edge_index (fully connected by construction; structure exploited analytically)
    const float* W_res   = (const float*)d_in[2];
    const float* b_res   = (const float*)d_in[3];
    const float* W_rel1  = (const float*)d_in[4];
    const float* b_rel1  = (const float*)d_in[5];
    const float* W_root1 = (const float*)d_in[6];
    const float* W_rel2  = (const float*)d_in[7];
    const float* b_rel2  = (const float*)d_in[8];
    const float* W_root2 = (const float*)d_in[9];
    const float* W_gat   = (const float*)d_in[10];
    const float* att_src = (const float*)d_in[11];
    const float* att_dst = (const float*)d_in[12];
    const float* b_gat   = (const float*)d_in[13];
    const float* W_fc    = (const float*)d_in[14];
    const float* b_fc    = (const float*)d_in[15];
    float* out = (float*)d_out;

    k_sumx<<<1, 224>>>(x);
    k_h1<<<N_BODIES, HID>>>(x, W_res, b_res, W_rel1, b_rel1, W_root1);
    k_part1<<<8, HID>>>();
    k_h2<<<N_BODIES, HID>>>(W_rel2, b_rel2, W_root2);
    k_gatpre<<<N_BODIES, 256>>>(W_gat, att_src, att_dst);
    k_gat<<<N_BODIES / 4, 256>>>(b_gat);
    k_matvec<<<KSPLITS, 768>>>(W_fc);
    k_reduce<<<OUT_DIM / 256, 256>>>(b_fc, out);
}

// round 3
// speedup vs baseline: 1.2707x; 1.2707x over previous
#include <cuda_runtime.h>
#include <cuda_bf16.h>

#define N_BODIES 512
#define HID 128
#define IN_DIM 7
#define OUT_DIM (N_BODIES * 6)      // 3072
#define KDIM (N_BODIES * HID)       // 65536
#define NEG_SLOPE 0.2f
#define KSPLITS 512

// ---- scratch (no allocations allowed) ----
__device__ float g_Sx[IN_DIM];
__device__ float g_c1[HID];              // S@W_rel1 + b_rel1 + b_res
__device__ float g_Wc1[IN_DIM * HID];    // W_root1 + W_res - W_rel1
__device__ float g_h1[N_BODIES * HID];
__device__ float g_p1[16 * HID];         // partial column sums of h1
__device__ float g_c2[HID];              // S1@W_rel2 + b_rel2
__device__ float g_Wd2[HID * HID];       // W_root2 - W_rel2
__device__ float g_h2[N_BODIES * HID];
__device__ float g_xh[N_BODIES * 2 * HID];   // GAT projected features [N,256]
__device__ float g_as[N_BODIES * 2];
__device__ float g_ad[N_BODIES * 2];
__device__ float g_h3[KDIM];             // final node features (flattened fc input)
__device__ float g_part[KSPLITS * OUT_DIM];  // 6 MB matvec partials
__device__ float g_part2[16 * OUT_DIM];

// ============================================================
// 1) column sums of x [512,7]
__global__ void k_sumx(const float* __restrict__ x) {
    int w = threadIdx.x >> 5, lane = threadIdx.x & 31;
    if (w < IN_DIM) {
        float s = 0.f;
        for (int i = lane; i < N_BODIES; i += 32) s += x[i * IN_DIM + w];
        #pragma unroll
        for (int o = 16; o; o >>= 1) s += __shfl_xor_sync(0xffffffffu, s, o);
        if (lane == 0) g_Sx[w] = s;
    }
}

// 2) prep layer1: c1 = S@W_rel1 + b_rel1 + b_res ; Wc1 = W_root1 + W_res - W_rel1
__global__ void k_prep1(const float* __restrict__ W_res, const float* __restrict__ b_res,
                        const float* __restrict__ W_rel1, const float* __restrict__ b_rel1,
                        const float* __restrict__ W_root1) {
    int c = threadIdx.x;
    float acc = b_rel1[c] + b_res[c];
    #pragma unroll
    for (int d = 0; d < IN_DIM; d++) {
        acc += g_Sx[d] * W_rel1[d * HID + c];
        g_Wc1[d * HID + c] = W_root1[d * HID + c] + W_res[d * HID + c] - W_rel1[d * HID + c];
    }
    g_c1[c] = acc;
}

// 3) h1 = relu(c1 + x@Wc1); 64 blocks x 8 rows, 128 threads
__global__ void k_h1(const float* __restrict__ x) {
    __shared__ float sx[8][IN_DIM];
    int r0 = blockIdx.x * 8, c = threadIdx.x;
    if (c < 8 * IN_DIM) sx[c / IN_DIM][c % IN_DIM] = x[r0 * IN_DIM + c];
    __syncthreads();
    float base = g_c1[c];
    #pragma unroll
    for (int r = 0; r < 8; r++) {
        float acc = base;
        #pragma unroll
        for (int d = 0; d < IN_DIM; d++) acc += sx[r][d] * g_Wc1[d * HID + c];
        g_h1[(r0 + r) * HID + c] = fmaxf(acc, 0.f);
    }
}

// 4) partial column sums of h1 (16 partials of 32 rows)
__global__ void k_part1() {
    int p = blockIdx.x, c = threadIdx.x;
    float s = 0.f;
    int i0 = p * 32;
    #pragma unroll 8
    for (int i = 0; i < 32; i++) s += g_h1[(i0 + i) * HID + c];
    g_p1[p * HID + c] = s;
}

// 5) Wd2 = W_root2 - W_rel2
__global__ void k_wd2(const float* __restrict__ W_rel2, const float* __restrict__ W_root2) {
    int i = blockIdx.x * 256 + threadIdx.x;
    g_Wd2[i] = W_root2[i] - W_rel2[i];
}

// 6) c2 = S1@W_rel2 + b_rel2
__global__ void k_prep2(const float* __restrict__ W_rel2, const float* __restrict__ b_rel2) {
    __shared__ float ss[HID];
    int c = threadIdx.x;
    float s = 0.f;
    #pragma unroll
    for (int p = 0; p < 16; p++) s += g_p1[p * HID + c];
    ss[c] = s;
    __syncthreads();
    float acc = b_rel2[c];
    #pragma unroll 4
    for (int d = 0; d < HID; d++) acc += ss[d] * W_rel2[d * HID + c];
    g_c2[c] = acc;
}

// 7) h2 = relu(c2 + h1@Wd2); tiled GEMM: 64 blocks x 8 rows x 128 cols, 256 threads
__global__ void __launch_bounds__(256) k_h2() {
    __shared__ float sh[8][HID];
    int r0 = blockIdx.x * 8;
    int t = threadIdx.x;
    // load 8x128 tile (4 elems/thread)
    #pragma unroll
    for (int q = 0; q < 4; q++) {
        int idx = t + q * 256;
        sh[idx >> 7][idx & 127] = g_h1[r0 * HID + idx];
    }
    __syncthreads();
    int c = t & 127, rg = (t >> 7) * 4;     // 4 rows per thread
    float a0 = 0.f, a1 = 0.f, a2 = 0.f, a3 = 0.f;
    #pragma unroll 4
    for (int d = 0; d < HID; d++) {
        float w = g_Wd2[d * HID + c];
        a0 += sh[rg + 0][d] * w;
        a1 += sh[rg + 1][d] * w;
        a2 += sh[rg + 2][d] * w;
        a3 += sh[rg + 3][d] * w;
    }
    float base = g_c2[c];
    g_h2[(r0 + rg + 0) * HID + c] = fmaxf(a0 + base, 0.f);
    g_h2[(r0 + rg + 1) * HID + c] = fmaxf(a1 + base, 0.f);
    g_h2[(r0 + rg + 2) * HID + c] = fmaxf(a2 + base, 0.f);
    g_h2[(r0 + rg + 3) * HID + c] = fmaxf(a3 + base, 0.f);
}

// 8) xh = h2 @ W_gat [512,256]; 64 blocks x 8 rows x 256 cols, 512 threads
__global__ void __launch_bounds__(512) k_xh(const float* __restrict__ W_gat) {
    __shared__ float sh[8][HID];
    int r0 = blockIdx.x * 8;
    int t = threadIdx.x;
    #pragma unroll
    for (int q = 0; q < 2; q++) {
        int idx = t + q * 512;
        sh[idx >> 7][idx & 127] = g_h2[r0 * HID + idx];
    }
    __syncthreads();
    int c = t & 255, rg = (t >> 8) * 4;
    float a0 = 0.f, a1 = 0.f, a2 = 0.f, a3 = 0.f;
    #pragma unroll 4
    for (int d = 0; d < HID; d++) {
        float w = W_gat[d * 256 + c];
        a0 += sh[rg + 0][d] * w;
        a1 += sh[rg + 1][d] * w;
        a2 += sh[rg + 2][d] * w;
        a3 += sh[rg + 3][d] * w;
    }
    g_xh[(r0 + rg + 0) * 256 + c] = a0;
    g_xh[(r0 + rg + 1) * 256 + c] = a1;
    g_xh[(r0 + rg + 2) * 256 + c] = a2;
    g_xh[(r0 + rg + 3) * 256 + c] = a3;
}

// 9) attention logits a_s, a_d per (node, head)
__global__ void k_logits(const float* __restrict__ att_src,
                         const float* __restrict__ att_dst) {
    int i = blockIdx.x, t = threadIdx.x;          // 256 threads
    __shared__ float red[256];
    float v = g_xh[i * 256 + t];
    int h = t >> 7, cc = t & 127;
    red[t] = v * att_src[h * HID + cc];
    __syncthreads();
    for (int o = 64; o >= 1; o >>= 1) {
        if (cc < o) red[t] += red[t + o];
        __syncthreads();
    }
    if (cc == 0) g_as[i * 2 + h] = red[t];
    __syncthreads();
    red[t] = v * att_dst[h * HID + cc];
    __syncthreads();
    for (int o = 64; o >= 1; o >>= 1) {
        if (cc < o) red[t] += red[t + o];
        __syncthreads();
    }
    if (cc == 0) g_ad[i * 2 + h] = red[t];
}

// 10) dense-softmax GAT aggregation: 4 dst nodes per block, 256 threads
__global__ void __launch_bounds__(256) k_gat(const float* __restrict__ b_gat) {
    __shared__ float al[8 * 512];    // alpha[pair = d*2+h][j], 16 KB
    int i0 = blockIdx.x * 4;
    int w = threadIdx.x >> 5, lane = threadIdx.x & 31;

    {   // warp w: softmax for pair (dst i0+w/2, head w&1)
        int d = w >> 1, h = w & 1;
        float ad = g_ad[(i0 + d) * 2 + h];
        float ev[16];
        float m = -1e30f;
        #pragma unroll
        for (int q = 0; q < 16; q++) {
            int j = lane + q * 32;
            float t = g_as[j * 2 + h] + ad;
            float e = t > 0.f ? t : NEG_SLOPE * t;
            ev[q] = e;
            m = fmaxf(m, e);
        }
        #pragma unroll
        for (int o = 16; o; o >>= 1) m = fmaxf(m, __shfl_xor_sync(0xffffffffu, m, o));
        float z = 0.f;
        #pragma unroll
        for (int q = 0; q < 16; q++) { float wv = __expf(ev[q] - m); ev[q] = wv; z += wv; }
        #pragma unroll
        for (int o = 16; o; o >>= 1) z += __shfl_xor_sync(0xffffffffu, z, o);
        float inv = 1.f / z;
        #pragma unroll
        for (int q = 0; q < 16; q++) al[w * 512 + lane + q * 32] = ev[q] * inv;
    }
    __syncthreads();

    int h = threadIdx.x >> 7;
    const float* xcol = g_xh + threadIdx.x;
    const float* A0 = al + (0 + h) * 512;
    const float* A1 = al + (2 + h) * 512;
    const float* A2 = al + (4 + h) * 512;
    const float* A3 = al + (6 + h) * 512;
    float a0 = 0.f, a1 = 0.f, a2 = 0.f, a3 = 0.f;
    #pragma unroll 4
    for (int j = 0; j < 512; j += 2) {
        float x0 = xcol[(size_t)j * 256];
        float x1 = xcol[(size_t)(j + 1) * 256];
        a0 += A0[j] * x0 + A0[j + 1] * x1;
        a1 += A1[j] * x0 + A1[j + 1] * x1;
        a2 += A2[j] * x0 + A2[j + 1] * x1;
        a3 += A3[j] * x0 + A3[j + 1] * x1;
    }
    __syncthreads();
    al[0 * 256 + threadIdx.x] = a0;
    al[1 * 256 + threadIdx.x] = a1;
    al[2 * 256 + threadIdx.x] = a2;
    al[3 * 256 + threadIdx.x] = a3;
    __syncthreads();
    if (threadIdx.x < HID) {
        int c = threadIdx.x;
        float bg = b_gat[c];
        #pragma unroll
        for (int d = 0; d < 4; d++) {
            float v = 0.5f * (al[d * 256 + c] + al[d * 256 + 128 + c]) + bg;
            g_h3[(i0 + d) * HID + c] = fmaxf(v, 0.f);
        }
    }
}

// 11) split-K matvec: 768 threads x float4 = 3072 cols; 512 K-splits of 128 rows
__global__ void __launch_bounds__(768) k_matvec(const float* __restrict__ Wfc) {
    int b = blockIdx.x, t = threadIdx.x;
    __shared__ float v[128];
    int k0 = b * 128;
    if (t < 128) v[t] = g_h3[k0 + t];
    __syncthreads();
    const float4* W4 = (const float4*)Wfc;     // row = 768 float4
    size_t base = (size_t)k0 * 768 + t;
    float4 s0 = {0,0,0,0}, s1 = {0,0,0,0}, s2 = {0,0,0,0}, s3 = {0,0,0,0};
    #pragma unroll 4
    for (int kk = 0; kk < 128; kk += 4) {
        float4 w0 = W4[base + (size_t)(kk + 0) * 768];
        float4 w1 = W4[base + (size_t)(kk + 1) * 768];
        float4 w2 = W4[base + (size_t)(kk + 2) * 768];
        float4 w3 = W4[base + (size_t)(kk + 3) * 768];
        float v0 = v[kk], v1 = v[kk + 1], v2 = v[kk + 2], v3 = v[kk + 3];
        s0.x += v0 * w0.x; s0.y += v0 * w0.y; s0.z += v0 * w0.z; s0.w += v0 * w0.w;
        s1.x += v1 * w1.x; s1.y += v1 * w1.y; s1.z += v1 * w1.z; s1.w += v1 * w1.w;
        s2.x += v2 * w2.x; s2.y += v2 * w2.y; s2.z += v2 * w2.z; s2.w += v2 * w2.w;
        s3.x += v3 * w3.x; s3.y += v3 * w3.y; s3.z += v3 * w3.z; s3.w += v3 * w3.w;
    }
    float4 r;
    r.x = s0.x + s1.x + s2.x + s3.x;
    r.y = s0.y + s1.y + s2.y + s3.y;
    r.z = s0.z + s1.z + s2.z + s3.z;
    r.w = s0.w + s1.w + s2.w + s3.w;
    ((float4*)g_part)[(size_t)b * 768 + t] = r;
}

// 12a) reduce stage 1: 512 -> 16 partials. 192 blocks.
__global__ void k_reduce1() {
    int b = blockIdx.x;
    int chunk = b / 12, obl = b % 12;
    int o = obl * 256 + threadIdx.x;
    float acc = 0.f;
    int s0 = chunk * 32;
    #pragma unroll 8
    for (int s = 0; s < 32; s++) acc += g_part[(size_t)(s0 + s) * OUT_DIM + o];
    g_part2[(size_t)chunk * OUT_DIM + o] = acc;
}

// 12b) reduce stage 2: 16 -> 1, add bias
__global__ void k_reduce2(const float* __restrict__ b_fc, float* __restrict__ out) {
    int o = blockIdx.x * 256 + threadIdx.x;
    float acc = b_fc[o];
    #pragma unroll
    for (int s = 0; s < 16; s++) acc += g_part2[(size_t)s * OUT_DIM + o];
    out[o] = acc;
}

extern "C" void kernel_launch(void* const* d_in, const int* in_sizes, int n_in,
                              void* d_out, int out_size) {
    const float* x       = (const float*)d_in[0];
    // d_in[1] = edge_index (fully connected by construction)
    const float* W_res   = (const float*)d_in[2];
    const float* b_res   = (const float*)d_in[3];
    const float* W_rel1  = (const float*)d_in[4];
    const float* b_rel1  = (const float*)d_in[5];
    const float* W_root1 = (const float*)d_in[6];
    const float* W_rel2  = (const float*)d_in[7];
    const float* b_rel2  = (const float*)d_in[8];
    const float* W_root2 = (const float*)d_in[9];
    const float* W_gat   = (const float*)d_in[10];
    const float* att_src = (const float*)d_in[11];
    const float* att_dst = (const float*)d_in[12];
    const float* b_gat   = (const float*)d_in[13];
    const float* W_fc    = (const float*)d_in[14];
    const float* b_fc    = (const float*)d_in[15];
    float* out = (float*)d_out;

    k_sumx<<<1, 224>>>(x);
    k_prep1<<<1, HID>>>(W_res, b_res, W_rel1, b_rel1, W_root1);
    k_h1<<<64, HID>>>(x);
    k_part1<<<16, HID>>>();
    k_wd2<<<64, 256>>>(W_rel2, W_root2);
    k_prep2<<<1, HID>>>(W_rel2, b_rel2);
    k_h2<<<64, 256>>>();
    k_xh<<<64, 512>>>(W_gat);
    k_logits<<<N_BODIES, 256>>>(att_src, att_dst);
    k_gat<<<N_BODIES / 4, 256>>>(b_gat);
    k_matvec<<<KSPLITS, 768>>>(W_fc);
    k_reduce1<<<192, 256>>>();
    k_reduce2<<<OUT_DIM / 256, 256>>>(b_fc, out);
}

// round 4
// speedup vs baseline: 1.4964x; 1.1776x over previous
#include <cuda_runtime.h>
#include <cuda_bf16.h>

#define N_BODIES 512
#define HID 128
#define IN_DIM 7
#define OUT_DIM (N_BODIES * 6)      // 3072
#define KDIM (N_BODIES * HID)       // 65536
#define NEG_SLOPE 0.2f
#define KSPLITS 256                  // 256 K-rows per split

// ---- scratch (no allocations allowed) ----
__device__ float g_Sx[IN_DIM];
__device__ float g_c1[HID];              // S@W_rel1 + b_rel1 + b_res
__device__ float g_Wc1[IN_DIM * HID];    // W_root1 + W_res - W_rel1
__device__ float g_h1[N_BODIES * HID];
__device__ float g_p1[64 * HID];         // per-block column sums of h1
__device__ float g_Wd2[HID * HID];       // W_root2 - W_rel2
__device__ float g_h2[N_BODIES * HID];
__device__ float g_xh[N_BODIES * 2 * HID];   // GAT projected features [N,256]
__device__ float g_as[N_BODIES * 2];
__device__ float g_ad[N_BODIES * 2];
__device__ float g_h3[KDIM];             // final node features (flattened fc input)
__device__ float g_part[KSPLITS * OUT_DIM];  // 3 MB matvec partials
__device__ float g_part2[8 * OUT_DIM];

// ============================================================
// K1: blocks 0..63 -> Wd2 = W_root2 - W_rel2 ; block 64 -> Sx, then c1/Wc1
__global__ void __launch_bounds__(256) k_prep(const float* __restrict__ x,
                      const float* __restrict__ W_res, const float* __restrict__ b_res,
                      const float* __restrict__ W_rel1, const float* __restrict__ b_rel1,
                      const float* __restrict__ W_root1,
                      const float* __restrict__ W_rel2, const float* __restrict__ W_root2) {
    if (blockIdx.x < 64) {
        int i = blockIdx.x * 256 + threadIdx.x;
        g_Wd2[i] = W_root2[i] - W_rel2[i];
        return;
    }
    // block 64: column sums of x [512,7]
    int w = threadIdx.x >> 5, lane = threadIdx.x & 31;
    if (w < IN_DIM) {
        float s = 0.f;
        for (int i = lane; i < N_BODIES; i += 32) s += x[i * IN_DIM + w];
        #pragma unroll
        for (int o = 16; o; o >>= 1) s += __shfl_xor_sync(0xffffffffu, s, o);
        if (lane == 0) g_Sx[w] = s;
    }
    __syncthreads();
    int c = threadIdx.x;
    if (c < HID) {
        float acc = b_rel1[c] + b_res[c];
        #pragma unroll
        for (int d = 0; d < IN_DIM; d++) {
            acc += g_Sx[d] * W_rel1[d * HID + c];
            g_Wc1[d * HID + c] = W_root1[d * HID + c] + W_res[d * HID + c] - W_rel1[d * HID + c];
        }
        g_c1[c] = acc;
    }
}

// K2: h1 = relu(c1 + x@Wc1) + per-block column sums. 64 blocks x 128 threads.
__global__ void __launch_bounds__(128) k_h1(const float* __restrict__ x) {
    __shared__ float sx[8][IN_DIM];
    int r0 = blockIdx.x * 8, c = threadIdx.x;
    if (c < 8 * IN_DIM) sx[c / IN_DIM][c % IN_DIM] = x[r0 * IN_DIM + c];
    __syncthreads();
    float base = g_c1[c];
    float wc[IN_DIM];
    #pragma unroll
    for (int d = 0; d < IN_DIM; d++) wc[d] = g_Wc1[d * HID + c];
    float colsum = 0.f;
    #pragma unroll
    for (int r = 0; r < 8; r++) {
        float acc = base;
        #pragma unroll
        for (int d = 0; d < IN_DIM; d++) acc += sx[r][d] * wc[d];
        acc = fmaxf(acc, 0.f);
        g_h1[(r0 + r) * HID + c] = acc;
        colsum += acc;
    }
    g_p1[blockIdx.x * HID + c] = colsum;
}

// K3: h2 = relu(c2 + h1@Wd2); c2 computed redundantly per block.
// 64 blocks x 256 threads, 8 rows each.
__global__ void __launch_bounds__(256) k_h2(const float* __restrict__ W_rel2,
                                            const float* __restrict__ b_rel2) {
    __shared__ float sh[8][HID];
    __shared__ float red[2][HID];
    __shared__ float sc2[HID];
    int t = threadIdx.x;
    int r0 = blockIdx.x * 8;
    // load 8x128 h1 tile
    #pragma unroll
    for (int q = 0; q < 4; q++) {
        int idx = t + q * 256;
        sh[idx >> 7][idx & 127] = g_h1[r0 * HID + idx];
    }
    // S1 = column sums of h1 (from 64 partials)
    {
        int c = t & 127, half = t >> 7;
        float s = 0.f;
        int p0 = half * 32;
        #pragma unroll 8
        for (int p = 0; p < 32; p++) s += g_p1[(p0 + p) * HID + c];
        red[half][c] = s;
    }
    __syncthreads();
    if (t < HID) {
        // S1 in register -> c2 = S1@W_rel2 + b_rel2 (redundant per block)
        __shared__ float S1[HID];
        S1[t] = red[0][t] + red[1][t];
        __syncthreads();
        float acc = b_rel2[t];
        #pragma unroll 4
        for (int d = 0; d < HID; d++) acc += S1[d] * W_rel2[d * HID + t];
        sc2[t] = acc;
    }
    __syncthreads();
    int c = t & 127, rg = (t >> 7) * 4;     // 4 rows per thread
    float a0 = 0.f, a1 = 0.f, a2 = 0.f, a3 = 0.f;
    #pragma unroll 4
    for (int d = 0; d < HID; d++) {
        float w = g_Wd2[d * HID + c];
        a0 += sh[rg + 0][d] * w;
        a1 += sh[rg + 1][d] * w;
        a2 += sh[rg + 2][d] * w;
        a3 += sh[rg + 3][d] * w;
    }
    float base = sc2[c];
    g_h2[(r0 + rg + 0) * HID + c] = fmaxf(a0 + base, 0.f);
    g_h2[(r0 + rg + 1) * HID + c] = fmaxf(a1 + base, 0.f);
    g_h2[(r0 + rg + 2) * HID + c] = fmaxf(a2 + base, 0.f);
    g_h2[(r0 + rg + 3) * HID + c] = fmaxf(a3 + base, 0.f);
}

// K4: xh = h2 @ W_gat [512,256] + attention logits. 64 blocks x 512 threads.
__global__ void __launch_bounds__(512) k_xh(const float* __restrict__ W_gat,
                                            const float* __restrict__ att_src,
                                            const float* __restrict__ att_dst) {
    __shared__ float sh[8][HID];     // h2 tile
    __shared__ float sxh[8][256];    // xh tile
    int r0 = blockIdx.x * 8;
    int t = threadIdx.x;
    #pragma unroll
    for (int q = 0; q < 2; q++) {
        int idx = t + q * 512;
        sh[idx >> 7][idx & 127] = g_h2[r0 * HID + idx];
    }
    __syncthreads();
    int c = t & 255, rg = (t >> 8) * 4;
    float a0 = 0.f, a1 = 0.f, a2 = 0.f, a3 = 0.f;
    #pragma unroll 4
    for (int d = 0; d < HID; d++) {
        float w = W_gat[d * 256 + c];
        a0 += sh[rg + 0][d] * w;
        a1 += sh[rg + 1][d] * w;
        a2 += sh[rg + 2][d] * w;
        a3 += sh[rg + 3][d] * w;
    }
    g_xh[(r0 + rg + 0) * 256 + c] = a0;  sxh[rg + 0][c] = a0;
    g_xh[(r0 + rg + 1) * 256 + c] = a1;  sxh[rg + 1][c] = a1;
    g_xh[(r0 + rg + 2) * 256 + c] = a2;  sxh[rg + 2][c] = a2;
    g_xh[(r0 + rg + 3) * 256 + c] = a3;  sxh[rg + 3][c] = a3;
    __syncthreads();
    // logits: warp w handles (row = w>>1, head = w&1); 16 warps
    int w = t >> 5, lane = t & 31;
    int row = w >> 1, h = w & 1;
    float ds = 0.f, dd = 0.f;
    #pragma unroll
    for (int q = 0; q < 4; q++) {
        int cc = lane + q * 32;
        float v = sxh[row][h * 128 + cc];
        ds += v * att_src[h * HID + cc];
        dd += v * att_dst[h * HID + cc];
    }
    #pragma unroll
    for (int o = 16; o; o >>= 1) {
        ds += __shfl_xor_sync(0xffffffffu, ds, o);
        dd += __shfl_xor_sync(0xffffffffu, dd, o);
    }
    if (lane == 0) {
        g_as[(r0 + row) * 2 + h] = ds;
        g_ad[(r0 + row) * 2 + h] = dd;
    }
}

// K5: dense-softmax GAT aggregation: 4 dst nodes per block, 256 threads
__global__ void __launch_bounds__(256) k_gat(const float* __restrict__ b_gat) {
    __shared__ float al[8 * 512];    // alpha[pair = d*2+h][j], 16 KB
    int i0 = blockIdx.x * 4;
    int w = threadIdx.x >> 5, lane = threadIdx.x & 31;

    {   // warp w: softmax for pair (dst i0+w/2, head w&1)
        int d = w >> 1, h = w & 1;
        float ad = g_ad[(i0 + d) * 2 + h];
        float ev[16];
        float m = -1e30f;
        #pragma unroll
        for (int q = 0; q < 16; q++) {
            int j = lane + q * 32;
            float t = g_as[j * 2 + h] + ad;
            float e = t > 0.f ? t : NEG_SLOPE * t;
            ev[q] = e;
            m = fmaxf(m, e);
        }
        #pragma unroll
        for (int o = 16; o; o >>= 1) m = fmaxf(m, __shfl_xor_sync(0xffffffffu, m, o));
        float z = 0.f;
        #pragma unroll
        for (int q = 0; q < 16; q++) { float wv = __expf(ev[q] - m); ev[q] = wv; z += wv; }
        #pragma unroll
        for (int o = 16; o; o >>= 1) z += __shfl_xor_sync(0xffffffffu, z, o);
        float inv = 1.f / z;
        #pragma unroll
        for (int q = 0; q < 16; q++) al[w * 512 + lane + q * 32] = ev[q] * inv;
    }
    __syncthreads();

    int h = threadIdx.x >> 7;
    const float* xcol = g_xh + threadIdx.x;
    const float* A0 = al + (0 + h) * 512;
    const float* A1 = al + (2 + h) * 512;
    const float* A2 = al + (4 + h) * 512;
    const float* A3 = al + (6 + h) * 512;
    float a0 = 0.f, a1 = 0.f, a2 = 0.f, a3 = 0.f;
    #pragma unroll 4
    for (int j = 0; j < 512; j += 2) {
        float x0 = xcol[(size_t)j * 256];
        float x1 = xcol[(size_t)(j + 1) * 256];
        a0 += A0[j] * x0 + A0[j + 1] * x1;
        a1 += A1[j] * x0 + A1[j + 1] * x1;
        a2 += A2[j] * x0 + A2[j + 1] * x1;
        a3 += A3[j] * x0 + A3[j + 1] * x1;
    }
    __syncthreads();
    al[0 * 256 + threadIdx.x] = a0;
    al[1 * 256 + threadIdx.x] = a1;
    al[2 * 256 + threadIdx.x] = a2;
    al[3 * 256 + threadIdx.x] = a3;
    __syncthreads();
    if (threadIdx.x < HID) {
        int c = threadIdx.x;
        float bg = b_gat[c];
        #pragma unroll
        for (int d = 0; d < 4; d++) {
            float v = 0.5f * (al[d * 256 + c] + al[d * 256 + 128 + c]) + bg;
            g_h3[(i0 + d) * HID + c] = fmaxf(v, 0.f);
        }
    }
}

// K6: split-K matvec: 768 threads x float4 = 3072 cols; 256 splits of 256 rows.
//     2 blocks/SM -> single resident wave. Streaming loads for W_fc.
__global__ void __launch_bounds__(768) k_matvec(const float* __restrict__ Wfc) {
    int b = blockIdx.x, t = threadIdx.x;
    __shared__ float v[256];
    int k0 = b * 256;
    if (t < 256) v[t] = g_h3[k0 + t];
    __syncthreads();
    const float4* W4 = (const float4*)Wfc;     // row = 768 float4
    size_t base = (size_t)k0 * 768 + t;
    float4 s0 = {0,0,0,0}, s1 = {0,0,0,0}, s2 = {0,0,0,0}, s3 = {0,0,0,0};
    #pragma unroll 4
    for (int kk = 0; kk < 256; kk += 4) {
        float4 w0 = __ldcs(&W4[base + (size_t)(kk + 0) * 768]);
        float4 w1 = __ldcs(&W4[base + (size_t)(kk + 1) * 768]);
        float4 w2 = __ldcs(&W4[base + (size_t)(kk + 2) * 768]);
        float4 w3 = __ldcs(&W4[base + (size_t)(kk + 3) * 768]);
        float v0 = v[kk], v1 = v[kk + 1], v2 = v[kk + 2], v3 = v[kk + 3];
        s0.x += v0 * w0.x; s0.y += v0 * w0.y; s0.z += v0 * w0.z; s0.w += v0 * w0.w;
        s1.x += v1 * w1.x; s1.y += v1 * w1.y; s1.z += v1 * w1.z; s1.w += v1 * w1.w;
        s2.x += v2 * w2.x; s2.y += v2 * w2.y; s2.z += v2 * w2.z; s2.w += v2 * w2.w;
        s3.x += v3 * w3.x; s3.y += v3 * w3.y; s3.z += v3 * w3.z; s3.w += v3 * w3.w;
    }
    float4 r;
    r.x = s0.x + s1.x + s2.x + s3.x;
    r.y = s0.y + s1.y + s2.y + s3.y;
    r.z = s0.z + s1.z + s2.z + s3.z;
    r.w = s0.w + s1.w + s2.w + s3.w;
    ((float4*)g_part)[(size_t)b * 768 + t] = r;
}

// K7a: reduce stage 1: 256 -> 8 partials. 96 blocks (12 o-blocks x 8 chunks).
__global__ void k_reduce1() {
    int b = blockIdx.x;
    int chunk = b & 7, obl = b >> 3;
    int o = obl * 256 + threadIdx.x;
    float acc = 0.f;
    int s0 = chunk * 32;
    #pragma unroll 8
    for (int s = 0; s < 32; s++) acc += g_part[(size_t)(s0 + s) * OUT_DIM + o];
    g_part2[(size_t)chunk * OUT_DIM + o] = acc;
}

// K7b: reduce stage 2: 8 -> 1, add bias. 12 blocks.
__global__ void k_reduce2(const float* __restrict__ b_fc, float* __restrict__ out) {
    int o = blockIdx.x * 256 + threadIdx.x;
    float acc = b_fc[o];
    #pragma unroll
    for (int s = 0; s < 8; s++) acc += g_part2[(size_t)s * OUT_DIM + o];
    out[o] = acc;
}

extern "C" void kernel_launch(void* const* d_in, const int* in_sizes, int n_in,
                              void* d_out, int out_size) {
    const float* x       = (const float*)d_in[0];
    // d_in[1] = edge_index (fully connected by construction)
    const float* W_res   = (const float*)d_in[2];
    const float* b_res   = (const float*)d_in[3];
    const float* W_rel1  = (const float*)d_in[4];
    const float* b_rel1  = (const float*)d_in[5];
    const float* W_root1 = (const float*)d_in[6];
    const float* W_rel2  = (const float*)d_in[7];
    const float* b_rel2  = (const float*)d_in[8];
    const float* W_root2 = (const float*)d_in[9];
    const float* W_gat   = (const float*)d_in[10];
    const float* att_src = (const float*)d_in[11];
    const float* att_dst = (const float*)d_in[12];
    const float* b_gat   = (const float*)d_in[13];
    const float* W_fc    = (const float*)d_in[14];
    const float* b_fc    = (const float*)d_in[15];
    float* out = (float*)d_out;

    k_prep<<<65, 256>>>(x, W_res, b_res, W_rel1, b_rel1, W_root1, W_rel2, W_root2);
    k_h1<<<64, 128>>>(x);
    k_h2<<<64, 256>>>(W_rel2, b_rel2);
    k_xh<<<64, 512>>>(W_gat, att_src, att_dst);
    k_gat<<<N_BODIES / 4, 256>>>(b_gat);
    k_matvec<<<KSPLITS, 768>>>(W_fc);
    k_reduce1<<<96, 256>>>();
    k_reduce2<<<OUT_DIM / 256, 256>>>(b_fc, out);
}